// round 1
// baseline (speedup 1.0000x reference)
#include <cuda_runtime.h>

// GRAPE qubit evolution: 20 commuting X-rotations collapse to one rotation
// with Theta = sum(a_k) * DT/2.  Pure streaming kernel, HBM-bound.
//
//   new0_real = c*r0 + s*m1     new0_imag = c*m0 - s*r1
//   new1_real = c*r1 + s*m0     new1_imag = c*m1 - s*r0
//
// Layout: state_real [2,B], state_imag [2,B].
// Output stack([real, imag]) -> [2,2,B]:
//   out[0      .. B   ) = real row0
//   out[B      .. 2B  ) = real row1
//   out[2B     .. 3B  ) = imag row0
//   out[3B     .. 4B  ) = imag row1

#define NUM_STEPS 20
#define DT_HALF   (0.5f * (1.0f / 20.0f))   // GATE_TIME/NUM_STEPS * 0.5
#define BATCH     8388608

__global__ __launch_bounds__(256) void grape_kernel(
    const float* __restrict__ amps,
    const float* __restrict__ sr,
    const float* __restrict__ si,
    float* __restrict__ out)
{
    // Theta: uniform across all threads; 20 broadcast loads, negligible.
    float theta = 0.0f;
#pragma unroll
    for (int k = 0; k < NUM_STEPS; k++) theta += __ldg(&amps[k]);
    theta *= DT_HALF;
    float c, s;
    __sincosf(theta, &s, &c);   // fast-math sincos; |theta| ~ 1, accurate enough
    // use precise versions to be safe on accuracy:
    c = cosf(theta);
    s = sinf(theta);

    const int i = blockIdx.x * blockDim.x + threadIdx.x;   // float4 index
    const int n4 = BATCH / 4;
    if (i >= n4) return;

    const float4* sr0 = (const float4*)sr;                  // row 0 real
    const float4* sr1 = (const float4*)(sr + BATCH);        // row 1 real
    const float4* si0 = (const float4*)si;                  // row 0 imag
    const float4* si1 = (const float4*)(si + BATCH);        // row 1 imag

    float4 r0 = __ldg(&sr0[i]);
    float4 r1 = __ldg(&sr1[i]);
    float4 m0 = __ldg(&si0[i]);
    float4 m1 = __ldg(&si1[i]);

    float4 o0r, o1r, o0i, o1i;
    o0r.x = c*r0.x + s*m1.x;  o0r.y = c*r0.y + s*m1.y;
    o0r.z = c*r0.z + s*m1.z;  o0r.w = c*r0.w + s*m1.w;

    o1r.x = c*r1.x + s*m0.x;  o1r.y = c*r1.y + s*m0.y;
    o1r.z = c*r1.z + s*m0.z;  o1r.w = c*r1.w + s*m0.w;

    o0i.x = c*m0.x - s*r1.x;  o0i.y = c*m0.y - s*r1.y;
    o0i.z = c*m0.z - s*r1.z;  o0i.w = c*m0.w - s*r1.w;

    o1i.x = c*m1.x - s*r0.x;  o1i.y = c*m1.y - s*r0.y;
    o1i.z = c*m1.z - s*r0.z;  o1i.w = c*m1.w - s*r0.w;

    float4* out0r = (float4*)out;                       // [0, B)
    float4* out1r = (float4*)(out + BATCH);             // [B, 2B)
    float4* out0i = (float4*)(out + 2 * (size_t)BATCH); // [2B, 3B)
    float4* out1i = (float4*)(out + 3 * (size_t)BATCH); // [3B, 4B)

    out0r[i] = o0r;
    out1r[i] = o1r;
    out0i[i] = o0i;
    out1i[i] = o1i;
}

extern "C" void kernel_launch(void* const* d_in, const int* in_sizes, int n_in,
                              void* d_out, int out_size)
{
    const float* amps = (const float*)d_in[0];  // [20]
    const float* sr   = (const float*)d_in[1];  // [2, B]
    const float* si   = (const float*)d_in[2];  // [2, B]
    float* out        = (float*)d_out;          // [2, 2, B]

    const int n4 = BATCH / 4;                   // 2,097,152 threads
    const int threads = 256;
    const int blocks = (n4 + threads - 1) / threads;   // 8192
    grape_kernel<<<blocks, threads>>>(amps, sr, si, out);
}

// round 2
// speedup vs baseline: 1.0043x; 1.0043x over previous
#include <cuda_runtime.h>

// GRAPE qubit evolution: 20 commuting X-rotations collapse to one rotation
// with Theta = sum(a_k) * DT/2.  Pure streaming kernel, HBM-bound.
//
//   new0_real = c*r0 + s*m1     new0_imag = c*m0 - s*r1
//   new1_real = c*r1 + s*m0     new1_imag = c*m1 - s*r0
//
// R1 -> R2: ILP=2 (8 front-batched float4 loads per thread) + __ldcs/__stcs
// streaming cache hints to deepen the DRAM queue and avoid L2 write-allocate
// churn. Target: DRAM 73.7% -> ~84%.

#define NUM_STEPS 20
#define DT_HALF   (0.5f * (1.0f / 20.0f))
#define BATCH     8388608

__device__ __forceinline__ float4 rot_add(float c, float s, float4 a, float4 b) {
    // c*a + s*b
    float4 r;
    r.x = fmaf(c, a.x, s * b.x);
    r.y = fmaf(c, a.y, s * b.y);
    r.z = fmaf(c, a.z, s * b.z);
    r.w = fmaf(c, a.w, s * b.w);
    return r;
}
__device__ __forceinline__ float4 rot_sub(float c, float s, float4 a, float4 b) {
    // c*a - s*b
    float4 r;
    r.x = fmaf(c, a.x, -s * b.x);
    r.y = fmaf(c, a.y, -s * b.y);
    r.z = fmaf(c, a.z, -s * b.z);
    r.w = fmaf(c, a.w, -s * b.w);
    return r;
}

__global__ __launch_bounds__(256) void grape_kernel(
    const float* __restrict__ amps,
    const float* __restrict__ sr,
    const float* __restrict__ si,
    float* __restrict__ out)
{
    float theta = 0.0f;
#pragma unroll
    for (int k = 0; k < NUM_STEPS; k++) theta += __ldg(&amps[k]);
    theta *= DT_HALF;
    const float c = cosf(theta);
    const float s = sinf(theta);

    const int n4   = BATCH / 4;          // 2,097,152 float4 columns
    const int half = n4 / 2;             // each thread does chunk i and i+half
    const int i = blockIdx.x * blockDim.x + threadIdx.x;
    if (i >= half) return;
    const int j = i + half;

    const float4* sr0 = (const float4*)sr;
    const float4* sr1 = (const float4*)(sr + BATCH);
    const float4* si0 = (const float4*)si;
    const float4* si1 = (const float4*)(si + BATCH);

    // Front-batch all 8 loads (MLP=8), streaming hint (no reuse).
    float4 r0a = __ldcs(&sr0[i]);
    float4 r1a = __ldcs(&sr1[i]);
    float4 m0a = __ldcs(&si0[i]);
    float4 m1a = __ldcs(&si1[i]);
    float4 r0b = __ldcs(&sr0[j]);
    float4 r1b = __ldcs(&sr1[j]);
    float4 m0b = __ldcs(&si0[j]);
    float4 m1b = __ldcs(&si1[j]);

    float4* out0r = (float4*)out;                        // [0, B)
    float4* out1r = (float4*)(out + (size_t)BATCH);      // [B, 2B)
    float4* out0i = (float4*)(out + 2 * (size_t)BATCH);  // [2B, 3B)
    float4* out1i = (float4*)(out + 3 * (size_t)BATCH);  // [3B, 4B)

    __stcs(&out0r[i], rot_add(c, s, r0a, m1a));
    __stcs(&out1r[i], rot_add(c, s, r1a, m0a));
    __stcs(&out0i[i], rot_sub(c, s, m0a, r1a));
    __stcs(&out1i[i], rot_sub(c, s, m1a, r0a));

    __stcs(&out0r[j], rot_add(c, s, r0b, m1b));
    __stcs(&out1r[j], rot_add(c, s, r1b, m0b));
    __stcs(&out0i[j], rot_sub(c, s, m0b, r1b));
    __stcs(&out1i[j], rot_sub(c, s, m1b, r0b));
}

extern "C" void kernel_launch(void* const* d_in, const int* in_sizes, int n_in,
                              void* d_out, int out_size)
{
    const float* amps = (const float*)d_in[0];  // [20]
    const float* sr   = (const float*)d_in[1];  // [2, B]
    const float* si   = (const float*)d_in[2];  // [2, B]
    float* out        = (float*)d_out;          // [2, 2, B]

    const int threads_total = BATCH / 8;        // 1,048,576 (two float4 per thread)
    const int threads = 256;
    const int blocks = threads_total / threads; // 4096
    grape_kernel<<<blocks, threads>>>(amps, sr, si, out);
}

// round 3
// speedup vs baseline: 1.0412x; 1.0368x over previous
#include <cuda_runtime.h>

// GRAPE qubit evolution: 20 commuting X-rotations collapse to one rotation
// with Theta = sum(a_k) * DT/2.  Pure streaming kernel, HBM-bound.
//
// R2 -> R3: the rotation factorizes into two independent stream pairs:
//   pair A: (r0, m1) -> out0r = c*r0 + s*m1 ; out1i = c*m1 - s*r0
//   pair B: (r1, m0) -> out1r = c*r1 + s*m0 ; out0i = c*m0 - s*r1
// Split the grid so each half touches only 2 read + 2 write streams
// (vs 4+4 in R1) to improve DRAM page locality. ILP=1, plain ldg/st
// (the R1 winner config; stcs and ILP=2 both regressed).

#define NUM_STEPS 20
#define DT_HALF   (0.5f * (1.0f / 20.0f))
#define BATCH     8388608

__global__ __launch_bounds__(256) void grape_kernel(
    const float* __restrict__ amps,
    const float* __restrict__ sr,
    const float* __restrict__ si,
    float* __restrict__ out)
{
    float theta = 0.0f;
#pragma unroll
    for (int k = 0; k < NUM_STEPS; k++) theta += __ldg(&amps[k]);
    theta *= DT_HALF;
    const float c = cosf(theta);
    const float s = sinf(theta);

    const int n4  = BATCH / 4;                 // 2,097,152 float4 columns
    const int tid = blockIdx.x * blockDim.x + threadIdx.x;

    if (tid < n4) {
        // ---- pair A: streams sr row0 + si row1 -> out0r, out1i ----
        const int i = tid;
        const float4* sr0 = (const float4*)sr;                       // read
        const float4* si1 = (const float4*)(si + (size_t)BATCH);     // read
        float4* out0r = (float4*)out;                                // write
        float4* out1i = (float4*)(out + 3 * (size_t)BATCH);          // write

        float4 a = __ldg(&sr0[i]);   // r0
        float4 b = __ldg(&si1[i]);   // m1

        float4 o0r, o1i;
        o0r.x = fmaf(c, a.x,  s * b.x);  o1i.x = fmaf(c, b.x, -s * a.x);
        o0r.y = fmaf(c, a.y,  s * b.y);  o1i.y = fmaf(c, b.y, -s * a.y);
        o0r.z = fmaf(c, a.z,  s * b.z);  o1i.z = fmaf(c, b.z, -s * a.z);
        o0r.w = fmaf(c, a.w,  s * b.w);  o1i.w = fmaf(c, b.w, -s * a.w);

        out0r[i] = o0r;
        out1i[i] = o1i;
    } else {
        // ---- pair B: streams sr row1 + si row0 -> out1r, out0i ----
        const int i = tid - n4;
        const float4* sr1 = (const float4*)(sr + (size_t)BATCH);     // read
        const float4* si0 = (const float4*)si;                       // read
        float4* out1r = (float4*)(out + (size_t)BATCH);              // write
        float4* out0i = (float4*)(out + 2 * (size_t)BATCH);          // write

        float4 a = __ldg(&sr1[i]);   // r1
        float4 b = __ldg(&si0[i]);   // m0

        float4 o1r, o0i;
        o1r.x = fmaf(c, a.x,  s * b.x);  o0i.x = fmaf(c, b.x, -s * a.x);
        o1r.y = fmaf(c, a.y,  s * b.y);  o0i.y = fmaf(c, b.y, -s * a.y);
        o1r.z = fmaf(c, a.z,  s * b.z);  o0i.z = fmaf(c, b.z, -s * a.z);
        o1r.w = fmaf(c, a.w,  s * b.w);  o0i.w = fmaf(c, b.w, -s * a.w);

        out1r[i] = o1r;
        out0i[i] = o0i;
    }
}

extern "C" void kernel_launch(void* const* d_in, const int* in_sizes, int n_in,
                              void* d_out, int out_size)
{
    const float* amps = (const float*)d_in[0];  // [20]
    const float* sr   = (const float*)d_in[1];  // [2, B]
    const float* si   = (const float*)d_in[2];  // [2, B]
    float* out        = (float*)d_out;          // [2, 2, B]

    const int n4 = BATCH / 4;                   // per-half thread count
    const int threads = 256;
    const int blocks = (2 * n4) / threads;      // 16384 blocks total
    grape_kernel<<<blocks, threads>>>(amps, sr, si, out);
}